// round 1
// baseline (speedup 1.0000x reference)
#include <cuda_runtime.h>

// Problem constants
constexpr int BB = 4;     // batch
constexpr int TQ = 256;   // query tokens
constexpr int TK = 1024;  // key tokens
constexpr int DD = 512;   // feature dim (qs = ms = 512)
constexpr int NA = 128;   // attention dim

// Scratch (allocation-free rule: __device__ globals)
__device__ float g_aq[BB * TQ * NA];   // 512 KB
__device__ float g_ak[BB * TK * NA];   // 2 MB

__device__ __forceinline__ float fast_tanh(float x) {
    float y;
    asm("tanh.approx.f32 %0, %1;" : "=f"(y) : "f"(x));
    return y;
}

// ---------------------------------------------------------------------------
// Generic tiled fp32 GEMM: C[M,N] = A[M,K] @ B[K,N], batched over blockIdx.z
// BM=64, BN=64, BK=16, 256 threads, 4x4 micro-tile per thread.
// ---------------------------------------------------------------------------
__global__ __launch_bounds__(256) void gemm_kernel(
    const float* __restrict__ A, const float* __restrict__ Bm,
    float* __restrict__ C,
    int M, int N, int K, long sA, long sB, long sC)
{
    constexpr int BM = 64, BN = 64, BK = 16;
    __shared__ float As[BK * (BM + 1)];   // [k][m] transposed, padded
    __shared__ float Bs[BK * BN];         // [k][n]

    A  += (long)blockIdx.z * sA;
    Bm += (long)blockIdx.z * sB;
    C  += (long)blockIdx.z * sC;

    const int tid = threadIdx.x;
    const int tx = tid & 15;    // col group (4 cols)
    const int ty = tid >> 4;    // row group (4 rows)
    const int m0 = blockIdx.y * BM;
    const int n0 = blockIdx.x * BN;

    float acc[4][4] = {};

    for (int k0 = 0; k0 < K; k0 += BK) {
        // Load A tile 64x16 (coalesced over k within a row chunk)
        #pragma unroll
        for (int i = 0; i < 4; i++) {
            int e  = tid + i * 256;
            int r  = e >> 4;      // /BK
            int kk = e & 15;
            As[kk * (BM + 1) + r] = A[(long)(m0 + r) * K + k0 + kk];
        }
        // Load B tile 16x64 (fully coalesced)
        #pragma unroll
        for (int i = 0; i < 4; i++) {
            int e  = tid + i * 256;
            int kk = e >> 6;      // /BN
            int c  = e & 63;
            Bs[kk * BN + c] = Bm[(long)(k0 + kk) * N + n0 + c];
        }
        __syncthreads();

        #pragma unroll
        for (int kk = 0; kk < BK; kk++) {
            float a0 = As[kk * (BM + 1) + 4 * ty + 0];
            float a1 = As[kk * (BM + 1) + 4 * ty + 1];
            float a2 = As[kk * (BM + 1) + 4 * ty + 2];
            float a3 = As[kk * (BM + 1) + 4 * ty + 3];
            float4 bv = *(const float4*)&Bs[kk * BN + 4 * tx];
            float b0 = bv.x, b1 = bv.y, b2 = bv.z, b3 = bv.w;
            acc[0][0] = fmaf(a0, b0, acc[0][0]); acc[0][1] = fmaf(a0, b1, acc[0][1]);
            acc[0][2] = fmaf(a0, b2, acc[0][2]); acc[0][3] = fmaf(a0, b3, acc[0][3]);
            acc[1][0] = fmaf(a1, b0, acc[1][0]); acc[1][1] = fmaf(a1, b1, acc[1][1]);
            acc[1][2] = fmaf(a1, b2, acc[1][2]); acc[1][3] = fmaf(a1, b3, acc[1][3]);
            acc[2][0] = fmaf(a2, b0, acc[2][0]); acc[2][1] = fmaf(a2, b1, acc[2][1]);
            acc[2][2] = fmaf(a2, b2, acc[2][2]); acc[2][3] = fmaf(a2, b3, acc[2][3]);
            acc[3][0] = fmaf(a3, b0, acc[3][0]); acc[3][1] = fmaf(a3, b1, acc[3][1]);
            acc[3][2] = fmaf(a3, b2, acc[3][2]); acc[3][3] = fmaf(a3, b3, acc[3][3]);
        }
        __syncthreads();
    }

    #pragma unroll
    for (int i = 0; i < 4; i++) {
        float4 o = make_float4(acc[i][0], acc[i][1], acc[i][2], acc[i][3]);
        *(float4*)&C[(long)(m0 + 4 * ty + i) * N + n0 + 4 * tx] = o;
    }
}

// ---------------------------------------------------------------------------
// Scores: scores[b,q,k] = sum_n v[n] * tanh(aq[b,q,n] + ak[b,k,n])
// Tile 64 q x 64 k per block, 256 threads, 4x4 micro-tile. MUFU.TANH-bound.
// ---------------------------------------------------------------------------
__global__ __launch_bounds__(256) void scores_kernel(
    const float* __restrict__ aq, const float* __restrict__ ak,
    const float* __restrict__ v, float* __restrict__ scores)
{
    extern __shared__ float sm[];
    constexpr int RS = NA + 1;   // 129: row stride (dodges bank conflicts)
    float* aq_s = sm;                 // [64][129]
    float* ak_s = sm + 64 * RS;       // [64][129]
    float* v_s  = sm + 128 * RS;      // [128]

    const int tid = threadIdx.x;
    const int b  = blockIdx.z;
    const int q0 = blockIdx.y * 64;
    const int k0 = blockIdx.x * 64;

    const float* aqg = aq + ((long)b * TQ + q0) * NA;
    const float* akg = ak + ((long)b * TK + k0) * NA;
    #pragma unroll
    for (int e = tid; e < 64 * NA; e += 256) {
        int r = e >> 7, n = e & 127;
        aq_s[r * RS + n] = aqg[e];
        ak_s[r * RS + n] = akg[e];
    }
    if (tid < NA) v_s[tid] = v[tid];
    __syncthreads();

    const int tx = tid & 15;   // k group
    const int ty = tid >> 4;   // q group
    const float* aqr = aq_s + 4 * ty * RS;
    const float* akr = ak_s + 4 * tx * RS;

    float acc[4][4] = {};
    #pragma unroll 4
    for (int n = 0; n < NA; n++) {
        float vn = v_s[n];
        float a0 = aqr[0 * RS + n], a1 = aqr[1 * RS + n];
        float a2 = aqr[2 * RS + n], a3 = aqr[3 * RS + n];
        float c0 = akr[0 * RS + n], c1 = akr[1 * RS + n];
        float c2 = akr[2 * RS + n], c3 = akr[3 * RS + n];
        acc[0][0] = fmaf(vn, fast_tanh(a0 + c0), acc[0][0]);
        acc[0][1] = fmaf(vn, fast_tanh(a0 + c1), acc[0][1]);
        acc[0][2] = fmaf(vn, fast_tanh(a0 + c2), acc[0][2]);
        acc[0][3] = fmaf(vn, fast_tanh(a0 + c3), acc[0][3]);
        acc[1][0] = fmaf(vn, fast_tanh(a1 + c0), acc[1][0]);
        acc[1][1] = fmaf(vn, fast_tanh(a1 + c1), acc[1][1]);
        acc[1][2] = fmaf(vn, fast_tanh(a1 + c2), acc[1][2]);
        acc[1][3] = fmaf(vn, fast_tanh(a1 + c3), acc[1][3]);
        acc[2][0] = fmaf(vn, fast_tanh(a2 + c0), acc[2][0]);
        acc[2][1] = fmaf(vn, fast_tanh(a2 + c1), acc[2][1]);
        acc[2][2] = fmaf(vn, fast_tanh(a2 + c2), acc[2][2]);
        acc[2][3] = fmaf(vn, fast_tanh(a2 + c3), acc[2][3]);
        acc[3][0] = fmaf(vn, fast_tanh(a3 + c0), acc[3][0]);
        acc[3][1] = fmaf(vn, fast_tanh(a3 + c1), acc[3][1]);
        acc[3][2] = fmaf(vn, fast_tanh(a3 + c2), acc[3][2]);
        acc[3][3] = fmaf(vn, fast_tanh(a3 + c3), acc[3][3]);
    }

    float* srow = scores + ((long)b * TQ + q0) * TK + k0;
    #pragma unroll
    for (int i = 0; i < 4; i++) {
        float4 o = make_float4(acc[i][0], acc[i][1], acc[i][2], acc[i][3]);
        *(float4*)&srow[(long)(4 * ty + i) * TK + 4 * tx] = o;
    }
}

// ---------------------------------------------------------------------------
// Row softmax over k=1024, in place. One block (256 threads) per (b,q) row.
// ---------------------------------------------------------------------------
__global__ __launch_bounds__(256) void softmax_kernel(float* __restrict__ w)
{
    __shared__ float red[8];
    float* p = w + (long)blockIdx.x * TK;
    const int tid = threadIdx.x;

    float4 x = *(const float4*)&p[tid * 4];
    float m = fmaxf(fmaxf(x.x, x.y), fmaxf(x.z, x.w));
    #pragma unroll
    for (int o = 16; o > 0; o >>= 1)
        m = fmaxf(m, __shfl_xor_sync(0xffffffffu, m, o));
    if ((tid & 31) == 0) red[tid >> 5] = m;
    __syncthreads();
    float gm = red[0];
    #pragma unroll
    for (int i = 1; i < 8; i++) gm = fmaxf(gm, red[i]);
    __syncthreads();

    float e0 = __expf(x.x - gm), e1 = __expf(x.y - gm);
    float e2 = __expf(x.z - gm), e3 = __expf(x.w - gm);
    float s = (e0 + e1) + (e2 + e3);
    #pragma unroll
    for (int o = 16; o > 0; o >>= 1)
        s += __shfl_xor_sync(0xffffffffu, s, o);
    if ((tid & 31) == 0) red[tid >> 5] = s;
    __syncthreads();
    float gs = 0.f;
    #pragma unroll
    for (int i = 0; i < 8; i++) gs += red[i];
    float inv = 1.0f / gs;

    float4 o4 = make_float4(e0 * inv, e1 * inv, e2 * inv, e3 * inv);
    *(float4*)&p[tid * 4] = o4;
}

// ---------------------------------------------------------------------------
extern "C" void kernel_launch(void* const* d_in, const int* in_sizes, int n_in,
                              void* d_out, int out_size)
{
    const float* query = (const float*)d_in[0];  // [4,256,512]
    const float* keys  = (const float*)d_in[1];  // [4,1024,512]
    const float* Wq    = (const float*)d_in[2];  // [512,128]
    const float* Wk    = (const float*)d_in[3];  // [512,128]
    const float* vatt  = (const float*)d_in[4];  // [128]

    float* out = (float*)d_out;
    float* ctx = out;                                  // [4,256,512]
    float* wts = out + (size_t)BB * TQ * DD;           // [4,256,1024]

    float *aq, *ak;
    cudaGetSymbolAddress((void**)&aq, g_aq);
    cudaGetSymbolAddress((void**)&ak, g_ak);

    const int smem = (128 * (NA + 1) + NA) * (int)sizeof(float);  // 66560 B
    cudaFuncSetAttribute(scores_kernel,
                         cudaFuncAttributeMaxDynamicSharedMemorySize, smem);

    // aq = query @ Wq : M=1024, N=128, K=512
    gemm_kernel<<<dim3(NA / 64, (BB * TQ) / 64, 1), 256>>>(
        query, Wq, aq, BB * TQ, NA, DD, 0, 0, 0);
    // ak = keys @ Wk : M=4096, N=128, K=512
    gemm_kernel<<<dim3(NA / 64, (BB * TK) / 64, 1), 256>>>(
        keys, Wk, ak, BB * TK, NA, DD, 0, 0, 0);
    // scores -> wts region
    scores_kernel<<<dim3(TK / 64, TQ / 64, BB), 256, smem>>>(aq, ak, vatt, wts);
    // softmax in place
    softmax_kernel<<<BB * TQ, 256>>>(wts);
    // context = weights @ keys : per batch M=256, N=512, K=1024
    gemm_kernel<<<dim3(DD / 64, TQ / 64, BB), 256>>>(
        wts, keys, ctx, TQ, DD, TK,
        (long)TQ * TK, (long)TK * DD, (long)TQ * DD);
}

// round 2
// speedup vs baseline: 1.3659x; 1.3659x over previous
#include <cuda_runtime.h>

constexpr int BB = 4;     // batch
constexpr int TQ = 256;   // query tokens
constexpr int TK = 1024;  // key tokens
constexpr int DD = 512;   // feature dim
constexpr int NA = 128;   // attention dim

// Scratch (allocation-free rule: __device__ globals)
__device__ float g_aq[BB * TQ * NA];   // 512 KB
__device__ float g_ak[BB * TK * NA];   // 2 MB

__device__ __forceinline__ float fast_tanh(float x) {
    float y;
    asm("tanh.approx.f32 %0, %1;" : "=f"(y) : "f"(x));
    return y;
}

// ---------------------------------------------------------------------------
// 64x64 fp32 GEMM tile, BK=16, 256 threads, 4x4 micro-tile,
// register-prefetch pipeline, float4 smem reads. ATOMIC -> atomicAdd epilogue.
// ---------------------------------------------------------------------------
template <bool ATOMIC>
__device__ __forceinline__ void gemm_tile(
    const float* __restrict__ A, const float* __restrict__ B,
    float* __restrict__ C, int ldA, int ldB, int ldC,
    int m0, int n0, int kBeg, int kEnd)
{
    __shared__ float As[16][68];   // [k][m], pad 4 keeps float4 alignment
    __shared__ float Bs[16][64];   // [k][n]

    const int tid = threadIdx.x;
    const int tx = tid & 15;       // n group (4 cols)
    const int ty = tid >> 4;       // m group (4 rows)

    // global-load assignment (one float4 each)
    const int ar  = tid >> 2;          // 0..63 (A row)
    const int akk = (tid & 3) * 4;     // 0,4,8,12 (A k offset)
    const int bkk = tid >> 4;          // 0..15 (B k row)
    const int bc  = (tid & 15) * 4;    // 0..60 (B col)

    const float* Aptr = A + (long)(m0 + ar) * ldA + kBeg + akk;
    const float* Bptr = B + (long)(kBeg + bkk) * ldB + n0 + bc;

    float4 aR = *(const float4*)Aptr;
    float4 bR = *(const float4*)Bptr;

    float acc[4][4] = {};
    const int nIter = (kEnd - kBeg) >> 4;

    for (int it = 0; it < nIter; it++) {
        As[akk + 0][ar] = aR.x;
        As[akk + 1][ar] = aR.y;
        As[akk + 2][ar] = aR.z;
        As[akk + 3][ar] = aR.w;
        *(float4*)&Bs[bkk][bc] = bR;
        __syncthreads();

        if (it + 1 < nIter) {   // prefetch next tile while computing
            aR = *(const float4*)(Aptr + (it + 1) * 16);
            bR = *(const float4*)(Bptr + (long)(it + 1) * 16 * ldB);
        }

        #pragma unroll
        for (int kk = 0; kk < 16; kk++) {
            float4 a = *(const float4*)&As[kk][4 * ty];
            float4 b = *(const float4*)&Bs[kk][4 * tx];
            acc[0][0] = fmaf(a.x, b.x, acc[0][0]);
            acc[0][1] = fmaf(a.x, b.y, acc[0][1]);
            acc[0][2] = fmaf(a.x, b.z, acc[0][2]);
            acc[0][3] = fmaf(a.x, b.w, acc[0][3]);
            acc[1][0] = fmaf(a.y, b.x, acc[1][0]);
            acc[1][1] = fmaf(a.y, b.y, acc[1][1]);
            acc[1][2] = fmaf(a.y, b.z, acc[1][2]);
            acc[1][3] = fmaf(a.y, b.w, acc[1][3]);
            acc[2][0] = fmaf(a.z, b.x, acc[2][0]);
            acc[2][1] = fmaf(a.z, b.y, acc[2][1]);
            acc[2][2] = fmaf(a.z, b.z, acc[2][2]);
            acc[2][3] = fmaf(a.z, b.w, acc[2][3]);
            acc[3][0] = fmaf(a.w, b.x, acc[3][0]);
            acc[3][1] = fmaf(a.w, b.y, acc[3][1]);
            acc[3][2] = fmaf(a.w, b.z, acc[3][2]);
            acc[3][3] = fmaf(a.w, b.w, acc[3][3]);
        }
        __syncthreads();
    }

    #pragma unroll
    for (int i = 0; i < 4; i++) {
        float* cp = C + (long)(m0 + 4 * ty + i) * ldC + n0 + 4 * tx;
        if (ATOMIC) {
            atomicAdd(cp + 0, acc[i][0]);
            atomicAdd(cp + 1, acc[i][1]);
            atomicAdd(cp + 2, acc[i][2]);
            atomicAdd(cp + 3, acc[i][3]);
        } else {
            *(float4*)cp = make_float4(acc[i][0], acc[i][1], acc[i][2], acc[i][3]);
        }
    }
}

// ---------------------------------------------------------------------------
// Both projections in ONE launch: 160 blocks (32 for aq, 128 for ak)
// ---------------------------------------------------------------------------
__global__ __launch_bounds__(256) void proj_kernel(
    const float* __restrict__ query, const float* __restrict__ keys,
    const float* __restrict__ Wq, const float* __restrict__ Wk,
    float* __restrict__ aq, float* __restrict__ ak)
{
    int gid = blockIdx.x;
    const float* A; const float* W; float* C; int t;
    if (gid < 32) { A = query; W = Wq; C = aq; t = gid; }
    else          { A = keys;  W = Wk; C = ak; t = gid - 32; }
    int mt = t >> 1, nt = t & 1;
    gemm_tile<false>(A, W, C, DD, NA, NA, mt * 64, nt * 64, 0, DD);
}

// ---------------------------------------------------------------------------
// Context GEMM, split-K=4: ctx[b] += wts[b][:, ks*256:(ks+1)*256] @ keys[b][...]
// grid (8 ntiles, 4 mtiles, 16 = b*4 + ks), atomicAdd epilogue.
// ---------------------------------------------------------------------------
__global__ __launch_bounds__(256) void ctx_kernel(
    const float* __restrict__ wts, const float* __restrict__ keys,
    float* __restrict__ ctx)
{
    int b = blockIdx.z >> 2, ks = blockIdx.z & 3;
    gemm_tile<true>(wts + (long)b * TQ * TK,
                    keys + (long)b * TK * DD,
                    ctx + (long)b * TQ * DD,
                    TK, DD, DD,
                    blockIdx.y * 64, blockIdx.x * 64,
                    ks * 256, ks * 256 + 256);
}

// ---------------------------------------------------------------------------
// Scores: scores[b,q,k] = sum_n v[n] * tanh(aq[b,q,n] + ak[b,k,n])
// Tile 64 q x 32 k, 256 threads, 2q x 4k micro-tile. 50KB smem -> 2 CTAs/SM.
// Also zeroes ctx (1 float4/thread) for the atomic context GEMM.
// ---------------------------------------------------------------------------
__global__ __launch_bounds__(256, 2) void scores_kernel(
    const float* __restrict__ aq, const float* __restrict__ ak,
    const float* __restrict__ v, float* __restrict__ scores,
    float* __restrict__ ctx)
{
    extern __shared__ float sm[];
    constexpr int RS = NA + 1;             // 129
    float* aq_s = sm;                      // [64][129]
    float* ak_s = sm + 64 * RS;            // [32][129]
    float* v_s  = sm + 96 * RS;            // [128]

    const int tid = threadIdx.x;
    const int b  = blockIdx.z;
    const int q0 = blockIdx.y * 64;
    const int k0 = blockIdx.x * 32;

    // zero ctx slice: 512 blocks x 256 threads x float4 = 2MB exactly
    {
        int bid = blockIdx.x + 32 * blockIdx.y + 128 * blockIdx.z;
        ((float4*)ctx)[bid * 256 + tid] = make_float4(0.f, 0.f, 0.f, 0.f);
    }

    const float* aqg = aq + ((long)b * TQ + q0) * NA;
    #pragma unroll
    for (int e = tid; e < 64 * NA; e += 256)
        aq_s[(e >> 7) * RS + (e & 127)] = aqg[e];
    const float* akg = ak + ((long)b * TK + k0) * NA;
    #pragma unroll
    for (int e = tid; e < 32 * NA; e += 256)
        ak_s[(e >> 7) * RS + (e & 127)] = akg[e];
    if (tid < NA) v_s[tid] = v[tid];
    __syncthreads();

    const int tx = tid & 7;    // k group (4 cols)
    const int ty = tid >> 3;   // q group (2 rows)
    const float* aqr = aq_s + 2 * ty * RS;
    const float* akr = ak_s + 4 * tx * RS;

    float acc[2][4] = {};
    #pragma unroll 4
    for (int n = 0; n < NA; n++) {
        float vn = v_s[n];
        float a0 = aqr[0 * RS + n], a1 = aqr[1 * RS + n];
        float c0 = akr[0 * RS + n], c1 = akr[1 * RS + n];
        float c2 = akr[2 * RS + n], c3 = akr[3 * RS + n];
        acc[0][0] = fmaf(vn, fast_tanh(a0 + c0), acc[0][0]);
        acc[0][1] = fmaf(vn, fast_tanh(a0 + c1), acc[0][1]);
        acc[0][2] = fmaf(vn, fast_tanh(a0 + c2), acc[0][2]);
        acc[0][3] = fmaf(vn, fast_tanh(a0 + c3), acc[0][3]);
        acc[1][0] = fmaf(vn, fast_tanh(a1 + c0), acc[1][0]);
        acc[1][1] = fmaf(vn, fast_tanh(a1 + c1), acc[1][1]);
        acc[1][2] = fmaf(vn, fast_tanh(a1 + c2), acc[1][2]);
        acc[1][3] = fmaf(vn, fast_tanh(a1 + c3), acc[1][3]);
    }

    float* srow = scores + ((long)b * TQ + q0 + 2 * ty) * TK + k0 + 4 * tx;
    *(float4*)srow        = make_float4(acc[0][0], acc[0][1], acc[0][2], acc[0][3]);
    *(float4*)(srow + TK) = make_float4(acc[1][0], acc[1][1], acc[1][2], acc[1][3]);
}

// ---------------------------------------------------------------------------
// Row softmax over k=1024, in place. One block (256 threads) per (b,q) row.
// ---------------------------------------------------------------------------
__global__ __launch_bounds__(256) void softmax_kernel(float* __restrict__ w)
{
    __shared__ float red[8];
    float* p = w + (long)blockIdx.x * TK;
    const int tid = threadIdx.x;

    float4 x = *(const float4*)&p[tid * 4];
    float m = fmaxf(fmaxf(x.x, x.y), fmaxf(x.z, x.w));
    #pragma unroll
    for (int o = 16; o > 0; o >>= 1)
        m = fmaxf(m, __shfl_xor_sync(0xffffffffu, m, o));
    if ((tid & 31) == 0) red[tid >> 5] = m;
    __syncthreads();
    float gm = red[0];
    #pragma unroll
    for (int i = 1; i < 8; i++) gm = fmaxf(gm, red[i]);
    __syncthreads();

    float e0 = __expf(x.x - gm), e1 = __expf(x.y - gm);
    float e2 = __expf(x.z - gm), e3 = __expf(x.w - gm);
    float s = (e0 + e1) + (e2 + e3);
    #pragma unroll
    for (int o = 16; o > 0; o >>= 1)
        s += __shfl_xor_sync(0xffffffffu, s, o);
    if ((tid & 31) == 0) red[tid >> 5] = s;
    __syncthreads();
    float gs = 0.f;
    #pragma unroll
    for (int i = 0; i < 8; i++) gs += red[i];
    float inv = 1.0f / gs;

    *(float4*)&p[tid * 4] = make_float4(e0 * inv, e1 * inv, e2 * inv, e3 * inv);
}

// ---------------------------------------------------------------------------
extern "C" void kernel_launch(void* const* d_in, const int* in_sizes, int n_in,
                              void* d_out, int out_size)
{
    const float* query = (const float*)d_in[0];  // [4,256,512]
    const float* keys  = (const float*)d_in[1];  // [4,1024,512]
    const float* Wq    = (const float*)d_in[2];  // [512,128]
    const float* Wk    = (const float*)d_in[3];  // [512,128]
    const float* vatt  = (const float*)d_in[4];  // [128]

    float* out = (float*)d_out;
    float* ctx = out;                                  // [4,256,512]
    float* wts = out + (size_t)BB * TQ * DD;           // [4,256,1024]

    float *aq, *ak;
    cudaGetSymbolAddress((void**)&aq, g_aq);
    cudaGetSymbolAddress((void**)&ak, g_ak);

    const int smem = (96 * (NA + 1) + NA) * (int)sizeof(float);  // 50048 B
    cudaFuncSetAttribute(scores_kernel,
                         cudaFuncAttributeMaxDynamicSharedMemorySize, smem);

    // 1) both projections, one wave
    proj_kernel<<<160, 256>>>(query, keys, Wq, Wk, aq, ak);
    // 2) scores (also zero-fills ctx for the atomic epilogue)
    scores_kernel<<<dim3(TK / 32, TQ / 64, BB), 256, smem>>>(aq, ak, vatt, wts, ctx);
    // 3) softmax in place
    softmax_kernel<<<BB * TQ, 256>>>(wts);
    // 4) context = weights @ keys, split-K=4, atomic accumulate
    ctx_kernel<<<dim3(DD / 64, TQ / 64, BB * 4), 256>>>(wts, keys, ctx);
}

// round 3
// speedup vs baseline: 1.5819x; 1.1582x over previous
#include <cuda_runtime.h>
#include <cuda_bf16.h>
#include <cstdint>

constexpr int BB = 4;     // batch
constexpr int TQ = 256;   // query tokens
constexpr int TK = 1024;  // key tokens
constexpr int DD = 512;   // feature dim
constexpr int NA = 128;   // attention dim

// Scratch (__device__ globals: allocation-free rule)
__device__ float g_aq[BB * TQ * NA];                 // 512 KB
__device__ float g_ak[BB * TK * NA];                 // 2 MB
__device__ __nv_bfloat16 g_whi[BB * TQ * TK];        // 2 MB
__device__ __nv_bfloat16 g_wlo[BB * TQ * TK];        // 2 MB
__device__ __nv_bfloat16 g_khi[BB * TK * DD];        // 4 MB
__device__ __nv_bfloat16 g_klo[BB * TK * DD];        // 4 MB

__device__ __forceinline__ float fast_tanh(float x) {
    float y;
    asm("tanh.approx.f32 %0, %1;" : "=f"(y) : "f"(x));
    return y;
}

__device__ __forceinline__ void ldsm_x4(uint32_t* r, uint32_t saddr) {
    asm volatile("ldmatrix.sync.aligned.m8n8.x4.shared.b16 {%0,%1,%2,%3}, [%4];"
                 : "=r"(r[0]), "=r"(r[1]), "=r"(r[2]), "=r"(r[3]) : "r"(saddr));
}
__device__ __forceinline__ void ldsm_x4_trans(uint32_t* r, uint32_t saddr) {
    asm volatile("ldmatrix.sync.aligned.m8n8.x4.trans.shared.b16 {%0,%1,%2,%3}, [%4];"
                 : "=r"(r[0]), "=r"(r[1]), "=r"(r[2]), "=r"(r[3]) : "r"(saddr));
}
__device__ __forceinline__ void mma16816(float* c, const uint32_t* a,
                                         const uint32_t* b) {
    asm volatile(
        "mma.sync.aligned.m16n8k16.row.col.f32.bf16.bf16.f32 "
        "{%0,%1,%2,%3}, {%4,%5,%6,%7}, {%8,%9}, {%0,%1,%2,%3};"
        : "+f"(c[0]), "+f"(c[1]), "+f"(c[2]), "+f"(c[3])
        : "r"(a[0]), "r"(a[1]), "r"(a[2]), "r"(a[3]), "r"(b[0]), "r"(b[1]));
}

// ---------------------------------------------------------------------------
// fp32 64x64 GEMM tile (for projections), BK=16, 256 thr, 4x4 micro-tile.
// ---------------------------------------------------------------------------
__device__ __forceinline__ void gemm_tile_f32(
    const float* __restrict__ A, const float* __restrict__ B,
    float* __restrict__ C, int ldA, int ldB, int ldC,
    int m0, int n0, int K)
{
    __shared__ float As[16][68];
    __shared__ float Bs[16][64];

    const int tid = threadIdx.x;
    const int tx = tid & 15;
    const int ty = tid >> 4;

    const int ar  = tid >> 2;
    const int akk = (tid & 3) * 4;
    const int bkk = tid >> 4;
    const int bc  = (tid & 15) * 4;

    const float* Aptr = A + (long)(m0 + ar) * ldA + akk;
    const float* Bptr = B + (long)bkk * ldB + n0 + bc;

    float4 aR = *(const float4*)Aptr;
    float4 bR = *(const float4*)Bptr;

    float acc[4][4] = {};
    const int nIter = K >> 4;

    for (int it = 0; it < nIter; it++) {
        As[akk + 0][ar] = aR.x;
        As[akk + 1][ar] = aR.y;
        As[akk + 2][ar] = aR.z;
        As[akk + 3][ar] = aR.w;
        *(float4*)&Bs[bkk][bc] = bR;
        __syncthreads();
        if (it + 1 < nIter) {
            aR = *(const float4*)(Aptr + (it + 1) * 16);
            bR = *(const float4*)(Bptr + (long)(it + 1) * 16 * ldB);
        }
        #pragma unroll
        for (int kk = 0; kk < 16; kk++) {
            float4 a = *(const float4*)&As[kk][4 * ty];
            float4 b = *(const float4*)&Bs[kk][4 * tx];
            acc[0][0] = fmaf(a.x, b.x, acc[0][0]);
            acc[0][1] = fmaf(a.x, b.y, acc[0][1]);
            acc[0][2] = fmaf(a.x, b.z, acc[0][2]);
            acc[0][3] = fmaf(a.x, b.w, acc[0][3]);
            acc[1][0] = fmaf(a.y, b.x, acc[1][0]);
            acc[1][1] = fmaf(a.y, b.y, acc[1][1]);
            acc[1][2] = fmaf(a.y, b.z, acc[1][2]);
            acc[1][3] = fmaf(a.y, b.w, acc[1][3]);
            acc[2][0] = fmaf(a.z, b.x, acc[2][0]);
            acc[2][1] = fmaf(a.z, b.y, acc[2][1]);
            acc[2][2] = fmaf(a.z, b.z, acc[2][2]);
            acc[2][3] = fmaf(a.z, b.w, acc[2][3]);
            acc[3][0] = fmaf(a.w, b.x, acc[3][0]);
            acc[3][1] = fmaf(a.w, b.y, acc[3][1]);
            acc[3][2] = fmaf(a.w, b.z, acc[3][2]);
            acc[3][3] = fmaf(a.w, b.w, acc[3][3]);
        }
        __syncthreads();
    }
    #pragma unroll
    for (int i = 0; i < 4; i++)
        *(float4*)&C[(long)(m0 + 4 * ty + i) * ldC + n0 + 4 * tx] =
            make_float4(acc[i][0], acc[i][1], acc[i][2], acc[i][3]);
}

// ---------------------------------------------------------------------------
// Fused launch: blocks [0,160) = projections; [160,672) = keys bf16 hi/lo conv
// ---------------------------------------------------------------------------
__global__ __launch_bounds__(256) void proj_conv_kernel(
    const float* __restrict__ query, const float* __restrict__ keys,
    const float* __restrict__ Wq, const float* __restrict__ Wk,
    float* __restrict__ aq, float* __restrict__ ak,
    __nv_bfloat16* __restrict__ khi, __nv_bfloat16* __restrict__ klo)
{
    int gid = blockIdx.x;
    if (gid < 160) {
        const float* A; const float* W; float* C; int t;
        if (gid < 32) { A = query; W = Wq; C = aq; t = gid; }
        else          { A = keys;  W = Wk; C = ak; t = gid - 32; }
        gemm_tile_f32(A, W, C, DD, NA, NA, (t >> 1) * 64, (t & 1) * 64, DD);
    } else {
        int cid = gid - 160;                 // 0..511
        int tid = threadIdx.x;
        #pragma unroll
        for (int j = 0; j < 4; j++) {
            long idx = (long)cid * 4096 + j * 1024 + tid * 4;
            float4 x = *(const float4*)&keys[idx];
            __nv_bfloat16 h0 = __float2bfloat16(x.x);
            __nv_bfloat16 h1 = __float2bfloat16(x.y);
            __nv_bfloat16 h2 = __float2bfloat16(x.z);
            __nv_bfloat16 h3 = __float2bfloat16(x.w);
            __nv_bfloat16 l0 = __float2bfloat16(x.x - __bfloat162float(h0));
            __nv_bfloat16 l1 = __float2bfloat16(x.y - __bfloat162float(h1));
            __nv_bfloat16 l2 = __float2bfloat16(x.z - __bfloat162float(h2));
            __nv_bfloat16 l3 = __float2bfloat16(x.w - __bfloat162float(h3));
            *(__nv_bfloat162*)&khi[idx]     = __nv_bfloat162(h0, h1);
            *(__nv_bfloat162*)&khi[idx + 2] = __nv_bfloat162(h2, h3);
            *(__nv_bfloat162*)&klo[idx]     = __nv_bfloat162(l0, l1);
            *(__nv_bfloat162*)&klo[idx + 2] = __nv_bfloat162(l2, l3);
        }
    }
}

// ---------------------------------------------------------------------------
// Scores: 64q x 32k tile, 256 threads, 2x4 micro-tile, MUFU.TANH-bound.
// ---------------------------------------------------------------------------
__global__ __launch_bounds__(256, 2) void scores_kernel(
    const float* __restrict__ aq, const float* __restrict__ ak,
    const float* __restrict__ v, float* __restrict__ scores)
{
    extern __shared__ float sm[];
    constexpr int RS = NA + 1;
    float* aq_s = sm;
    float* ak_s = sm + 64 * RS;
    float* v_s  = sm + 96 * RS;

    const int tid = threadIdx.x;
    const int b  = blockIdx.z;
    const int q0 = blockIdx.y * 64;
    const int k0 = blockIdx.x * 32;

    const float* aqg = aq + ((long)b * TQ + q0) * NA;
    #pragma unroll
    for (int e = tid; e < 64 * NA; e += 256)
        aq_s[(e >> 7) * RS + (e & 127)] = aqg[e];
    const float* akg = ak + ((long)b * TK + k0) * NA;
    #pragma unroll
    for (int e = tid; e < 32 * NA; e += 256)
        ak_s[(e >> 7) * RS + (e & 127)] = akg[e];
    if (tid < NA) v_s[tid] = v[tid];
    __syncthreads();

    const int tx = tid & 7;
    const int ty = tid >> 3;
    const float* aqr = aq_s + 2 * ty * RS;
    const float* akr = ak_s + 4 * tx * RS;

    float acc[2][4] = {};
    #pragma unroll 4
    for (int n = 0; n < NA; n++) {
        float vn = v_s[n];
        float a0 = aqr[0 * RS + n], a1 = aqr[1 * RS + n];
        float c0 = akr[0 * RS + n], c1 = akr[1 * RS + n];
        float c2 = akr[2 * RS + n], c3 = akr[3 * RS + n];
        acc[0][0] = fmaf(vn, fast_tanh(a0 + c0), acc[0][0]);
        acc[0][1] = fmaf(vn, fast_tanh(a0 + c1), acc[0][1]);
        acc[0][2] = fmaf(vn, fast_tanh(a0 + c2), acc[0][2]);
        acc[0][3] = fmaf(vn, fast_tanh(a0 + c3), acc[0][3]);
        acc[1][0] = fmaf(vn, fast_tanh(a1 + c0), acc[1][0]);
        acc[1][1] = fmaf(vn, fast_tanh(a1 + c1), acc[1][1]);
        acc[1][2] = fmaf(vn, fast_tanh(a1 + c2), acc[1][2]);
        acc[1][3] = fmaf(vn, fast_tanh(a1 + c3), acc[1][3]);
    }

    float* srow = scores + ((long)b * TQ + q0 + 2 * ty) * TK + k0 + 4 * tx;
    *(float4*)srow        = make_float4(acc[0][0], acc[0][1], acc[0][2], acc[0][3]);
    *(float4*)(srow + TK) = make_float4(acc[1][0], acc[1][1], acc[1][2], acc[1][3]);
}

// ---------------------------------------------------------------------------
// Row softmax over k=1024, in place; also emits bf16 hi/lo weight splits.
// ---------------------------------------------------------------------------
__global__ __launch_bounds__(256) void softmax_kernel(
    float* __restrict__ w,
    __nv_bfloat16* __restrict__ whi, __nv_bfloat16* __restrict__ wlo)
{
    __shared__ float red[8];
    float* p = w + (long)blockIdx.x * TK;
    const int tid = threadIdx.x;

    float4 x = *(const float4*)&p[tid * 4];
    float m = fmaxf(fmaxf(x.x, x.y), fmaxf(x.z, x.w));
    #pragma unroll
    for (int o = 16; o > 0; o >>= 1)
        m = fmaxf(m, __shfl_xor_sync(0xffffffffu, m, o));
    if ((tid & 31) == 0) red[tid >> 5] = m;
    __syncthreads();
    float gm = red[0];
    #pragma unroll
    for (int i = 1; i < 8; i++) gm = fmaxf(gm, red[i]);
    __syncthreads();

    float e0 = __expf(x.x - gm), e1 = __expf(x.y - gm);
    float e2 = __expf(x.z - gm), e3 = __expf(x.w - gm);
    float s = (e0 + e1) + (e2 + e3);
    #pragma unroll
    for (int o = 16; o > 0; o >>= 1)
        s += __shfl_xor_sync(0xffffffffu, s, o);
    if ((tid & 31) == 0) red[tid >> 5] = s;
    __syncthreads();
    float gs = 0.f;
    #pragma unroll
    for (int i = 0; i < 8; i++) gs += red[i];
    float inv = 1.0f / gs;

    float w0 = e0 * inv, w1 = e1 * inv, w2 = e2 * inv, w3 = e3 * inv;
    *(float4*)&p[tid * 4] = make_float4(w0, w1, w2, w3);

    long base = (long)blockIdx.x * TK + tid * 4;
    __nv_bfloat16 h0 = __float2bfloat16(w0), h1 = __float2bfloat16(w1);
    __nv_bfloat16 h2 = __float2bfloat16(w2), h3 = __float2bfloat16(w3);
    __nv_bfloat16 l0 = __float2bfloat16(w0 - __bfloat162float(h0));
    __nv_bfloat16 l1 = __float2bfloat16(w1 - __bfloat162float(h1));
    __nv_bfloat16 l2 = __float2bfloat16(w2 - __bfloat162float(h2));
    __nv_bfloat16 l3 = __float2bfloat16(w3 - __bfloat162float(h3));
    *(__nv_bfloat162*)&whi[base]     = __nv_bfloat162(h0, h1);
    *(__nv_bfloat162*)&whi[base + 2] = __nv_bfloat162(h2, h3);
    *(__nv_bfloat162*)&wlo[base]     = __nv_bfloat162(l0, l1);
    *(__nv_bfloat162*)&wlo[base + 2] = __nv_bfloat162(l2, l3);
}

// ---------------------------------------------------------------------------
// Context GEMM via HMMA (mma.sync m16n8k16 bf16, fp32 acc), split-precision:
// ctx = Whi*Khi + Whi*Klo + Wlo*Khi.
// CTA 64x64, 128 threads (4 warps, 32x32 warp tile), BK=32, full K per block.
// ---------------------------------------------------------------------------
__global__ __launch_bounds__(128) void ctx_mma_kernel(
    const __nv_bfloat16* __restrict__ whi, const __nv_bfloat16* __restrict__ wlo,
    const __nv_bfloat16* __restrict__ khi, const __nv_bfloat16* __restrict__ klo,
    float* __restrict__ ctx)
{
    __shared__ __nv_bfloat16 Ws[2][64][40];   // [hi/lo][m][k], row pad 16B
    __shared__ __nv_bfloat16 Ks[2][32][72];   // [hi/lo][k][n], row pad 16B

    const int tid  = threadIdx.x;
    const int lane = tid & 31;
    const int wid  = tid >> 5;
    const int b    = blockIdx.z;
    const int m0   = blockIdx.y * 64;
    const int n0   = blockIdx.x * 64;
    const int wm   = (wid >> 1) * 32;
    const int wn   = (wid & 1) * 32;

    const __nv_bfloat16* Wb[2] = { whi + (long)b * TQ * TK,
                                   wlo + (long)b * TQ * TK };
    const __nv_bfloat16* Kb[2] = { khi + (long)b * TK * DD,
                                   klo + (long)b * TK * DD };

    // global-load assignment
    const int wrow0 = tid >> 2, wchk = tid & 3;          // + second at tid+128
    const int krow0 = tid >> 3, kchk = tid & 7;

    int4 wpre[2][2], kpre[2][2];
    #pragma unroll
    for (int h = 0; h < 2; h++) {
        wpre[h][0] = ((const int4*)(Wb[h] + (long)(m0 + wrow0) * TK))[wchk];
        wpre[h][1] = ((const int4*)(Wb[h] + (long)(m0 + wrow0 + 32) * TK))[wchk];
        kpre[h][0] = ((const int4*)(Kb[h] + (long)krow0 * DD + n0))[kchk];
        kpre[h][1] = ((const int4*)(Kb[h] + (long)(krow0 + 16) * DD + n0))[kchk];
    }

    float acc[2][4][4] = {};

    uint32_t ws_base = (uint32_t)__cvta_generic_to_shared(&Ws[0][0][0]);
    uint32_t ks_base = (uint32_t)__cvta_generic_to_shared(&Ks[0][0][0]);

    for (int it = 0; it < TK / 32; it++) {
        // stage smem
        #pragma unroll
        for (int h = 0; h < 2; h++) {
            *(int4*)&Ws[h][wrow0][wchk * 8]      = wpre[h][0];
            *(int4*)&Ws[h][wrow0 + 32][wchk * 8] = wpre[h][1];
            *(int4*)&Ks[h][krow0][kchk * 8]      = kpre[h][0];
            *(int4*)&Ks[h][krow0 + 16][kchk * 8] = kpre[h][1];
        }
        __syncthreads();

        if (it + 1 < TK / 32) {
            int kg = (it + 1) * 32;
            #pragma unroll
            for (int h = 0; h < 2; h++) {
                wpre[h][0] = ((const int4*)(Wb[h] + (long)(m0 + wrow0) * TK + kg))[wchk];
                wpre[h][1] = ((const int4*)(Wb[h] + (long)(m0 + wrow0 + 32) * TK + kg))[wchk];
                kpre[h][0] = ((const int4*)(Kb[h] + (long)(kg + krow0) * DD + n0))[kchk];
                kpre[h][1] = ((const int4*)(Kb[h] + (long)(kg + krow0 + 16) * DD + n0))[kchk];
            }
        }

        #pragma unroll
        for (int ks = 0; ks < 32; ks += 16) {
            uint32_t afr[2][2][4];  // [hi/lo][m-tile][4]
            uint32_t bfr[2][2][4];  // [hi/lo][n16-pair][4]
            // A fragments: row = wm + tm*16 + (lane&15), col = ks + (lane>>4)*8
            #pragma unroll
            for (int h = 0; h < 2; h++)
                #pragma unroll
                for (int tm = 0; tm < 2; tm++) {
                    uint32_t addr = ws_base +
                        2u * ((h * 64 * 40) +
                              (wm + tm * 16 + (lane & 15)) * 40 +
                              ks + (lane >> 4) * 8);
                    ldsm_x4(afr[h][tm], addr);
                }
            // B fragments (trans): krow = ks + (lane&7) + ((lane>>3)&1)*8,
            //                      ncol = wn + tp*16 + (lane>>4)*8
            #pragma unroll
            for (int h = 0; h < 2; h++)
                #pragma unroll
                for (int tp = 0; tp < 2; tp++) {
                    uint32_t addr = ks_base +
                        2u * ((h * 32 * 72) +
                              (ks + (lane & 7) + ((lane >> 3) & 1) * 8) * 72 +
                              wn + tp * 16 + (lane >> 4) * 8);
                    ldsm_x4_trans(bfr[h][tp], addr);
                }
            // MMAs: hi*hi + hi*lo + lo*hi
            #pragma unroll
            for (int tm = 0; tm < 2; tm++)
                #pragma unroll
                for (int tn = 0; tn < 4; tn++) {
                    uint32_t* bh = &bfr[0][tn >> 1][(tn & 1) * 2];
                    uint32_t* bl = &bfr[1][tn >> 1][(tn & 1) * 2];
                    mma16816(acc[tm][tn], afr[0][tm], bh);
                    mma16816(acc[tm][tn], afr[0][tm], bl);
                    mma16816(acc[tm][tn], afr[1][tm], bh);
                }
        }
        __syncthreads();
    }

    // epilogue
    float* cb = ctx + (long)b * TQ * DD;
    #pragma unroll
    for (int tm = 0; tm < 2; tm++)
        #pragma unroll
        for (int tn = 0; tn < 4; tn++) {
            int row = m0 + wm + tm * 16 + (lane >> 2);
            int col = n0 + wn + tn * 8 + 2 * (lane & 3);
            *(float2*)&cb[(long)row * DD + col] =
                make_float2(acc[tm][tn][0], acc[tm][tn][1]);
            *(float2*)&cb[(long)(row + 8) * DD + col] =
                make_float2(acc[tm][tn][2], acc[tm][tn][3]);
        }
}

// ---------------------------------------------------------------------------
extern "C" void kernel_launch(void* const* d_in, const int* in_sizes, int n_in,
                              void* d_out, int out_size)
{
    const float* query = (const float*)d_in[0];
    const float* keys  = (const float*)d_in[1];
    const float* Wq    = (const float*)d_in[2];
    const float* Wk    = (const float*)d_in[3];
    const float* vatt  = (const float*)d_in[4];

    float* out = (float*)d_out;
    float* ctx = out;                           // [4,256,512]
    float* wts = out + (size_t)BB * TQ * DD;    // [4,256,1024]

    float *aq, *ak;
    __nv_bfloat16 *whi, *wlo, *khi, *klo;
    cudaGetSymbolAddress((void**)&aq, g_aq);
    cudaGetSymbolAddress((void**)&ak, g_ak);
    cudaGetSymbolAddress((void**)&whi, g_whi);
    cudaGetSymbolAddress((void**)&wlo, g_wlo);
    cudaGetSymbolAddress((void**)&khi, g_khi);
    cudaGetSymbolAddress((void**)&klo, g_klo);

    const int smem = (96 * (NA + 1) + NA) * (int)sizeof(float);  // 50048 B
    cudaFuncSetAttribute(scores_kernel,
                         cudaFuncAttributeMaxDynamicSharedMemorySize, smem);

    // 1) projections (160 blocks) + keys bf16 split (512 blocks), one wave
    proj_conv_kernel<<<672, 256>>>(query, keys, Wq, Wk, aq, ak, khi, klo);
    // 2) scores
    scores_kernel<<<dim3(TK / 32, TQ / 64, BB), 256, smem>>>(aq, ak, vatt, wts);
    // 3) softmax (also emits weight bf16 splits)
    softmax_kernel<<<BB * TQ, 256>>>(wts, whi, wlo);
    // 4) context via tensor cores, full-K per block
    ctx_mma_kernel<<<dim3(DD / 64, TQ / 64, BB), 128>>>(whi, wlo, khi, klo, ctx);
}

// round 4
// speedup vs baseline: 2.0200x; 1.2769x over previous
#include <cuda_runtime.h>
#include <cuda_bf16.h>
#include <cstdint>

constexpr int BB = 4;     // batch
constexpr int TQ = 256;   // query tokens
constexpr int TK = 1024;  // key tokens
constexpr int DD = 512;   // feature dim
constexpr int NA = 128;   // attention dim
constexpr int XR = BB * TQ + BB * TK;   // 5120 combined rows (query; keys)

// Scratch (__device__ globals: allocation-free rule)
__device__ __nv_bfloat16 g_xhi[XR * DD];       // 5 MB  (query rows 0..1023, keys rows 1024..5119)
__device__ __nv_bfloat16 g_xlo[XR * DD];       // 5 MB
__device__ __nv_bfloat16 g_wq_hi[DD * NA];     // 128 KB
__device__ __nv_bfloat16 g_wq_lo[DD * NA];
__device__ __nv_bfloat16 g_wk_hi[DD * NA];
__device__ __nv_bfloat16 g_wk_lo[DD * NA];
__device__ float         g_p0[XR * NA];        // 2.5 MB proj split-K partial 0
__device__ float         g_p1[XR * NA];        // 2.5 MB proj split-K partial 1
__device__ __nv_bfloat16 g_whi[BB * TQ * TK];  // 2 MB  softmax weights hi
__device__ __nv_bfloat16 g_wlo[BB * TQ * TK];  // 2 MB  softmax weights lo

__device__ __forceinline__ float fast_tanh(float x) {
    float y;
    asm("tanh.approx.f32 %0, %1;" : "=f"(y) : "f"(x));
    return y;
}

__device__ __forceinline__ void ldsm_x4(uint32_t* r, uint32_t saddr) {
    asm volatile("ldmatrix.sync.aligned.m8n8.x4.shared.b16 {%0,%1,%2,%3}, [%4];"
                 : "=r"(r[0]), "=r"(r[1]), "=r"(r[2]), "=r"(r[3]) : "r"(saddr));
}
__device__ __forceinline__ void ldsm_x4_trans(uint32_t* r, uint32_t saddr) {
    asm volatile("ldmatrix.sync.aligned.m8n8.x4.trans.shared.b16 {%0,%1,%2,%3}, [%4];"
                 : "=r"(r[0]), "=r"(r[1]), "=r"(r[2]), "=r"(r[3]) : "r"(saddr));
}
__device__ __forceinline__ void mma16816(float* c, const uint32_t* a,
                                         const uint32_t* b) {
    asm volatile(
        "mma.sync.aligned.m16n8k16.row.col.f32.bf16.bf16.f32 "
        "{%0,%1,%2,%3}, {%4,%5,%6,%7}, {%8,%9}, {%0,%1,%2,%3};"
        : "+f"(c[0]), "+f"(c[1]), "+f"(c[2]), "+f"(c[3])
        : "r"(a[0]), "r"(a[1]), "r"(a[2]), "r"(a[3]), "r"(b[0]), "r"(b[1]));
}

// ---------------------------------------------------------------------------
// 64x64 bf16-split (3-pass: hi*hi + hi*lo + lo*hi) MMA tile, fp32 acc.
// 128 threads / 4 warps, 32x32 warp tiles, BK=32, register prefetch.
// ---------------------------------------------------------------------------
template <bool ATOMIC>
__device__ __forceinline__ void mma_tile3(
    const __nv_bfloat16* __restrict__ Ahi, const __nv_bfloat16* __restrict__ Alo,
    int ldA,
    const __nv_bfloat16* __restrict__ Bhi, const __nv_bfloat16* __restrict__ Blo,
    int ldB,
    float* __restrict__ C, int ldC,
    int m0, int n0, int kBeg, int nIter)
{
    __shared__ __nv_bfloat16 As[2][64][40];   // [hi/lo][m][k], row pad 16B
    __shared__ __nv_bfloat16 Bs[2][32][72];   // [hi/lo][k][n], row pad 16B

    const int tid  = threadIdx.x;
    const int lane = tid & 31;
    const int wid  = tid >> 5;
    const int wm   = (wid >> 1) * 32;
    const int wn   = (wid & 1) * 32;

    const __nv_bfloat16* Ab[2] = { Ahi, Alo };
    const __nv_bfloat16* Bb[2] = { Bhi, Blo };

    const int arow0 = tid >> 2, achk = tid & 3;   // + second row at +32
    const int brow0 = tid >> 3, bchk = tid & 7;   // + second row at +16

    int4 apre[2][2], bpre[2][2];
    #pragma unroll
    for (int h = 0; h < 2; h++) {
        apre[h][0] = ((const int4*)(Ab[h] + (long)(m0 + arow0) * ldA + kBeg))[achk];
        apre[h][1] = ((const int4*)(Ab[h] + (long)(m0 + arow0 + 32) * ldA + kBeg))[achk];
        bpre[h][0] = ((const int4*)(Bb[h] + (long)(kBeg + brow0) * ldB + n0))[bchk];
        bpre[h][1] = ((const int4*)(Bb[h] + (long)(kBeg + brow0 + 16) * ldB + n0))[bchk];
    }

    float acc[2][4][4] = {};
    uint32_t as_base = (uint32_t)__cvta_generic_to_shared(&As[0][0][0]);
    uint32_t bs_base = (uint32_t)__cvta_generic_to_shared(&Bs[0][0][0]);

    for (int it = 0; it < nIter; it++) {
        #pragma unroll
        for (int h = 0; h < 2; h++) {
            *(int4*)&As[h][arow0][achk * 8]      = apre[h][0];
            *(int4*)&As[h][arow0 + 32][achk * 8] = apre[h][1];
            *(int4*)&Bs[h][brow0][bchk * 8]      = bpre[h][0];
            *(int4*)&Bs[h][brow0 + 16][bchk * 8] = bpre[h][1];
        }
        __syncthreads();

        if (it + 1 < nIter) {
            int kg = kBeg + (it + 1) * 32;
            #pragma unroll
            for (int h = 0; h < 2; h++) {
                apre[h][0] = ((const int4*)(Ab[h] + (long)(m0 + arow0) * ldA + kg))[achk];
                apre[h][1] = ((const int4*)(Ab[h] + (long)(m0 + arow0 + 32) * ldA + kg))[achk];
                bpre[h][0] = ((const int4*)(Bb[h] + (long)(kg + brow0) * ldB + n0))[bchk];
                bpre[h][1] = ((const int4*)(Bb[h] + (long)(kg + brow0 + 16) * ldB + n0))[bchk];
            }
        }

        #pragma unroll
        for (int ks = 0; ks < 32; ks += 16) {
            uint32_t afr[2][2][4];
            uint32_t bfr[2][2][4];
            #pragma unroll
            for (int h = 0; h < 2; h++)
                #pragma unroll
                for (int tm = 0; tm < 2; tm++) {
                    uint32_t addr = as_base +
                        2u * ((h * 64 * 40) +
                              (wm + tm * 16 + (lane & 15)) * 40 +
                              ks + (lane >> 4) * 8);
                    ldsm_x4(afr[h][tm], addr);
                }
            #pragma unroll
            for (int h = 0; h < 2; h++)
                #pragma unroll
                for (int tp = 0; tp < 2; tp++) {
                    uint32_t addr = bs_base +
                        2u * ((h * 32 * 72) +
                              (ks + (lane & 7) + ((lane >> 3) & 1) * 8) * 72 +
                              wn + tp * 16 + (lane >> 4) * 8);
                    ldsm_x4_trans(bfr[h][tp], addr);
                }
            #pragma unroll
            for (int tm = 0; tm < 2; tm++)
                #pragma unroll
                for (int tn = 0; tn < 4; tn++) {
                    uint32_t* bh = &bfr[0][tn >> 1][(tn & 1) * 2];
                    uint32_t* bl = &bfr[1][tn >> 1][(tn & 1) * 2];
                    mma16816(acc[tm][tn], afr[0][tm], bh);
                    mma16816(acc[tm][tn], afr[0][tm], bl);
                    mma16816(acc[tm][tn], afr[1][tm], bh);
                }
        }
        __syncthreads();
    }

    #pragma unroll
    for (int tm = 0; tm < 2; tm++)
        #pragma unroll
        for (int tn = 0; tn < 4; tn++) {
            int row = m0 + wm + tm * 16 + (lane >> 2);
            int col = n0 + wn + tn * 8 + 2 * (lane & 3);
            float* c0 = C + (long)row * ldC + col;
            float* c1 = C + (long)(row + 8) * ldC + col;
            if (ATOMIC) {
                atomicAdd(c0 + 0, acc[tm][tn][0]);
                atomicAdd(c0 + 1, acc[tm][tn][1]);
                atomicAdd(c1 + 0, acc[tm][tn][2]);
                atomicAdd(c1 + 1, acc[tm][tn][3]);
            } else {
                *(float2*)c0 = make_float2(acc[tm][tn][0], acc[tm][tn][1]);
                *(float2*)c1 = make_float2(acc[tm][tn][2], acc[tm][tn][3]);
            }
        }
}

// ---------------------------------------------------------------------------
// Convert: query+keys -> x hi/lo (combined), Wq/Wk -> hi/lo. 2688 blocks.
// ---------------------------------------------------------------------------
__global__ __launch_bounds__(256) void convert_kernel(
    const float* __restrict__ query, const float* __restrict__ keys,
    const float* __restrict__ Wq, const float* __restrict__ Wk,
    __nv_bfloat16* __restrict__ xhi, __nv_bfloat16* __restrict__ xlo,
    __nv_bfloat16* __restrict__ wqhi, __nv_bfloat16* __restrict__ wqlo,
    __nv_bfloat16* __restrict__ wkhi, __nv_bfloat16* __restrict__ wklo)
{
    const int bid = blockIdx.x, tid = threadIdx.x;
    const float* src; __nv_bfloat16 *dhi, *dlo; long e;
    if (bid < 512) {                 // query -> x rows [0,1024)
        e = (long)bid * 1024 + tid * 4;
        src = query; dhi = xhi; dlo = xlo;
    } else if (bid < 2560) {         // keys -> x rows [1024,5120)
        e = (long)(bid - 512) * 1024 + tid * 4;
        src = keys; dhi = xhi + (long)BB * TQ * DD; dlo = xlo + (long)BB * TQ * DD;
    } else if (bid < 2624) {         // Wq
        e = (long)(bid - 2560) * 1024 + tid * 4;
        src = Wq; dhi = wqhi; dlo = wqlo;
    } else {                          // Wk
        e = (long)(bid - 2624) * 1024 + tid * 4;
        src = Wk; dhi = wkhi; dlo = wklo;
    }
    float4 x = *(const float4*)&src[e];
    __nv_bfloat16 h0 = __float2bfloat16(x.x), h1 = __float2bfloat16(x.y);
    __nv_bfloat16 h2 = __float2bfloat16(x.z), h3 = __float2bfloat16(x.w);
    __nv_bfloat16 l0 = __float2bfloat16(x.x - __bfloat162float(h0));
    __nv_bfloat16 l1 = __float2bfloat16(x.y - __bfloat162float(h1));
    __nv_bfloat16 l2 = __float2bfloat16(x.z - __bfloat162float(h2));
    __nv_bfloat16 l3 = __float2bfloat16(x.w - __bfloat162float(h3));
    *(__nv_bfloat162*)&dhi[e]     = __nv_bfloat162(h0, h1);
    *(__nv_bfloat162*)&dhi[e + 2] = __nv_bfloat162(h2, h3);
    *(__nv_bfloat162*)&dlo[e]     = __nv_bfloat162(l0, l1);
    *(__nv_bfloat162*)&dlo[e + 2] = __nv_bfloat162(l2, l3);
}

// ---------------------------------------------------------------------------
// Projections via HMMA: p[s] = x[:, s*256:(s+1)*256] @ W[s*256:...]
// grid (2 n-tiles, 80 m-tiles, 2 splitK). W chosen by row range.
// ---------------------------------------------------------------------------
__global__ __launch_bounds__(128, 4) void proj_mma_kernel(
    const __nv_bfloat16* __restrict__ xhi, const __nv_bfloat16* __restrict__ xlo,
    const __nv_bfloat16* __restrict__ wqhi, const __nv_bfloat16* __restrict__ wqlo,
    const __nv_bfloat16* __restrict__ wkhi, const __nv_bfloat16* __restrict__ wklo,
    float* __restrict__ p0, float* __restrict__ p1)
{
    const int m0 = blockIdx.y * 64;
    const int n0 = blockIdx.x * 64;
    const int ks = blockIdx.z;
    const bool isQ = (m0 < BB * TQ);
    mma_tile3<false>(xhi, xlo, DD,
                     isQ ? wqhi : wkhi, isQ ? wqlo : wklo, NA,
                     ks ? p1 : p0, NA,
                     m0, n0, ks * 256, 8);
}

// ---------------------------------------------------------------------------
// Context GEMM via HMMA, split-K=4, atomicAdd epilogue (ctx zeroed in scores).
// ---------------------------------------------------------------------------
__global__ __launch_bounds__(128, 4) void ctx_mma_kernel(
    const __nv_bfloat16* __restrict__ whi, const __nv_bfloat16* __restrict__ wlo,
    const __nv_bfloat16* __restrict__ xhi, const __nv_bfloat16* __restrict__ xlo,
    float* __restrict__ ctx)
{
    const int b  = blockIdx.z >> 2;
    const int ks = blockIdx.z & 3;
    const long kbase = (long)(BB * TQ + b * TK) * DD;   // keys rows of x, batch b
    mma_tile3<true>(whi + (long)b * TQ * TK, wlo + (long)b * TQ * TK, TK,
                    xhi + kbase, xlo + kbase, DD,
                    ctx + (long)b * TQ * DD, DD,
                    blockIdx.y * 64, blockIdx.x * 64, ks * 256, 8);
}

// ---------------------------------------------------------------------------
// Scores: 64q x 32k tile, 2x4 micro-tile, MUFU.TANH-bound.
// Sums the two proj split-K partials while staging smem; zeroes ctx.
// ---------------------------------------------------------------------------
__global__ __launch_bounds__(256, 2) void scores_kernel(
    const float* __restrict__ p0, const float* __restrict__ p1,
    const float* __restrict__ v, float* __restrict__ scores,
    float* __restrict__ ctx)
{
    extern __shared__ float sm[];
    constexpr int RS = NA + 1;
    float* aq_s = sm;
    float* ak_s = sm + 64 * RS;
    float* v_s  = sm + 96 * RS;

    const int tid = threadIdx.x;
    const int b  = blockIdx.z;
    const int q0 = blockIdx.y * 64;
    const int k0 = blockIdx.x * 32;

    // zero ctx: 512 blocks x 256 threads x 1 float4 = 2MB exactly
    {
        int bid = blockIdx.x + 32 * blockIdx.y + 128 * blockIdx.z;
        ((float4*)ctx)[bid * 256 + tid] = make_float4(0.f, 0.f, 0.f, 0.f);
    }

    const long qbase = (long)(b * TQ + q0) * NA;
    #pragma unroll
    for (int e = tid; e < 64 * NA; e += 256)
        aq_s[(e >> 7) * RS + (e & 127)] = p0[qbase + e] + p1[qbase + e];
    const long kbase = (long)(BB * TQ + b * TK + k0) * NA;
    #pragma unroll
    for (int e = tid; e < 32 * NA; e += 256)
        ak_s[(e >> 7) * RS + (e & 127)] = p0[kbase + e] + p1[kbase + e];
    if (tid < NA) v_s[tid] = v[tid];
    __syncthreads();

    const int tx = tid & 7;
    const int ty = tid >> 3;
    const float* aqr = aq_s + 2 * ty * RS;
    const float* akr = ak_s + 4 * tx * RS;

    float acc[2][4] = {};
    #pragma unroll 4
    for (int n = 0; n < NA; n++) {
        float vn = v_s[n];
        float a0 = aqr[0 * RS + n], a1 = aqr[1 * RS + n];
        float c0 = akr[0 * RS + n], c1 = akr[1 * RS + n];
        float c2 = akr[2 * RS + n], c3 = akr[3 * RS + n];
        acc[0][0] = fmaf(vn, fast_tanh(a0 + c0), acc[0][0]);
        acc[0][1] = fmaf(vn, fast_tanh(a0 + c1), acc[0][1]);
        acc[0][2] = fmaf(vn, fast_tanh(a0 + c2), acc[0][2]);
        acc[0][3] = fmaf(vn, fast_tanh(a0 + c3), acc[0][3]);
        acc[1][0] = fmaf(vn, fast_tanh(a1 + c0), acc[1][0]);
        acc[1][1] = fmaf(vn, fast_tanh(a1 + c1), acc[1][1]);
        acc[1][2] = fmaf(vn, fast_tanh(a1 + c2), acc[1][2]);
        acc[1][3] = fmaf(vn, fast_tanh(a1 + c3), acc[1][3]);
    }

    float* srow = scores + ((long)b * TQ + q0 + 2 * ty) * TK + k0 + 4 * tx;
    *(float4*)srow        = make_float4(acc[0][0], acc[0][1], acc[0][2], acc[0][3]);
    *(float4*)(srow + TK) = make_float4(acc[1][0], acc[1][1], acc[1][2], acc[1][3]);
}

// ---------------------------------------------------------------------------
// Row softmax over k=1024, in place; emits bf16 hi/lo weight splits.
// ---------------------------------------------------------------------------
__global__ __launch_bounds__(256) void softmax_kernel(
    float* __restrict__ w,
    __nv_bfloat16* __restrict__ whi, __nv_bfloat16* __restrict__ wlo)
{
    __shared__ float red[8];
    float* p = w + (long)blockIdx.x * TK;
    const int tid = threadIdx.x;

    float4 x = *(const float4*)&p[tid * 4];
    float m = fmaxf(fmaxf(x.x, x.y), fmaxf(x.z, x.w));
    #pragma unroll
    for (int o = 16; o > 0; o >>= 1)
        m = fmaxf(m, __shfl_xor_sync(0xffffffffu, m, o));
    if ((tid & 31) == 0) red[tid >> 5] = m;
    __syncthreads();
    float gm = red[0];
    #pragma unroll
    for (int i = 1; i < 8; i++) gm = fmaxf(gm, red[i]);
    __syncthreads();

    float e0 = __expf(x.x - gm), e1 = __expf(x.y - gm);
    float e2 = __expf(x.z - gm), e3 = __expf(x.w - gm);
    float s = (e0 + e1) + (e2 + e3);
    #pragma unroll
    for (int o = 16; o > 0; o >>= 1)
        s += __shfl_xor_sync(0xffffffffu, s, o);
    if ((tid & 31) == 0) red[tid >> 5] = s;
    __syncthreads();
    float gs = 0.f;
    #pragma unroll
    for (int i = 0; i < 8; i++) gs += red[i];
    float inv = 1.0f / gs;

    float w0 = e0 * inv, w1 = e1 * inv, w2 = e2 * inv, w3 = e3 * inv;
    *(float4*)&p[tid * 4] = make_float4(w0, w1, w2, w3);

    long base = (long)blockIdx.x * TK + tid * 4;
    __nv_bfloat16 h0 = __float2bfloat16(w0), h1 = __float2bfloat16(w1);
    __nv_bfloat16 h2 = __float2bfloat16(w2), h3 = __float2bfloat16(w3);
    __nv_bfloat16 l0 = __float2bfloat16(w0 - __bfloat162float(h0));
    __nv_bfloat16 l1 = __float2bfloat16(w1 - __bfloat162float(h1));
    __nv_bfloat16 l2 = __float2bfloat16(w2 - __bfloat162float(h2));
    __nv_bfloat16 l3 = __float2bfloat16(w3 - __bfloat162float(h3));
    *(__nv_bfloat162*)&whi[base]     = __nv_bfloat162(h0, h1);
    *(__nv_bfloat162*)&whi[base + 2] = __nv_bfloat162(h2, h3);
    *(__nv_bfloat162*)&wlo[base]     = __nv_bfloat162(l0, l1);
    *(__nv_bfloat162*)&wlo[base + 2] = __nv_bfloat162(l2, l3);
}

// ---------------------------------------------------------------------------
extern "C" void kernel_launch(void* const* d_in, const int* in_sizes, int n_in,
                              void* d_out, int out_size)
{
    const float* query = (const float*)d_in[0];
    const float* keys  = (const float*)d_in[1];
    const float* Wq    = (const float*)d_in[2];
    const float* Wk    = (const float*)d_in[3];
    const float* vatt  = (const float*)d_in[4];

    float* out = (float*)d_out;
    float* ctx = out;                           // [4,256,512]
    float* wts = out + (size_t)BB * TQ * DD;    // [4,256,1024]

    __nv_bfloat16 *xhi, *xlo, *wqhi, *wqlo, *wkhi, *wklo, *whi, *wlo;
    float *p0, *p1;
    cudaGetSymbolAddress((void**)&xhi, g_xhi);
    cudaGetSymbolAddress((void**)&xlo, g_xlo);
    cudaGetSymbolAddress((void**)&wqhi, g_wq_hi);
    cudaGetSymbolAddress((void**)&wqlo, g_wq_lo);
    cudaGetSymbolAddress((void**)&wkhi, g_wk_hi);
    cudaGetSymbolAddress((void**)&wklo, g_wk_lo);
    cudaGetSymbolAddress((void**)&p0, g_p0);
    cudaGetSymbolAddress((void**)&p1, g_p1);
    cudaGetSymbolAddress((void**)&whi, g_whi);
    cudaGetSymbolAddress((void**)&wlo, g_wlo);

    const int smem = (96 * (NA + 1) + NA) * (int)sizeof(float);  // 50048 B
    cudaFuncSetAttribute(scores_kernel,
                         cudaFuncAttributeMaxDynamicSharedMemorySize, smem);

    // 1) fp32 -> bf16 hi/lo splits (query+keys combined, Wq, Wk)
    convert_kernel<<<2688, 256>>>(query, keys, Wq, Wk,
                                  xhi, xlo, wqhi, wqlo, wkhi, wklo);
    // 2) projections via tensor cores, split-K=2 -> partials p0,p1
    proj_mma_kernel<<<dim3(2, 80, 2), 128>>>(xhi, xlo, wqhi, wqlo, wkhi, wklo,
                                             p0, p1);
    // 3) scores (sums partials, zeroes ctx)
    scores_kernel<<<dim3(TK / 32, TQ / 64, BB), 256, smem>>>(p0, p1, vatt, wts, ctx);
    // 4) softmax (emits weight hi/lo)
    softmax_kernel<<<BB * TQ, 256>>>(wts, whi, wlo);
    // 5) context via tensor cores, split-K=4, atomic accumulate
    ctx_mma_kernel<<<dim3(DD / 64, TQ / 64, BB * 4), 128>>>(whi, wlo, xhi, xlo, ctx);
}